// round 2
// baseline (speedup 1.0000x reference)
#include <cuda_runtime.h>
#include <cuda_fp16.h>
#include <cstdint>

#define B_DIM  8192
#define IN_DIM 1024
#define H_DIM  1024
#define KTOT   2048
#define N4H    4096
#define BH     (B_DIM * H_DIM)

// ---------------- device scratch (static globals: allocation-free) ----------
__device__ __align__(1024) __half g_A[(size_t)B_DIM * KTOT];   // [8192,2048] fp16  [x | h]
__device__ __align__(1024) __half g_W[(size_t)N4H * KTOT];     // [4096,2048] fp16, row = 4*h+gate, cols [Wx | Wh]
__device__ __align__(1024) float  g_bias[N4H];                 // interleaved 4*h+gate (i,f,g,o)

// ---------------- PTX helpers ----------------------------------------------
__device__ __forceinline__ uint32_t smem_u32(const void* p) {
    uint32_t a;
    asm("{ .reg .u64 t; cvta.to.shared.u64 t, %1; cvt.u32.u64 %0, t; }" : "=r"(a) : "l"(p));
    return a;
}
#define CP16(sm, gp) \
    asm volatile("cp.async.cg.shared.global [%0], [%1], 16;" :: "r"(sm), "l"(gp) : "memory")
#define CP_COMMIT() asm volatile("cp.async.commit_group;" ::: "memory")
#define CP_WAIT(n)  asm volatile("cp.async.wait_group %0;" :: "n"(n) : "memory")

#define LDSM_X4(r, addr)                                                        \
    asm volatile("ldmatrix.sync.aligned.m8n8.x4.shared.b16 {%0,%1,%2,%3}, [%4];" \
        : "=r"((r)[0]), "=r"((r)[1]), "=r"((r)[2]), "=r"((r)[3]) : "r"(addr))

#define MMA16816(c, a, b0, b1)                                                  \
    asm volatile("mma.sync.aligned.m16n8k16.row.col.f32.f16.f16.f32 "           \
        "{%0,%1,%2,%3}, {%4,%5,%6,%7}, {%8,%9}, {%0,%1,%2,%3};"                 \
        : "+f"((c)[0]), "+f"((c)[1]), "+f"((c)[2]), "+f"((c)[3])                \
        : "r"((a)[0]), "r"((a)[1]), "r"((a)[2]), "r"((a)[3]), "r"(b0), "r"(b1))

__device__ __forceinline__ float sigf(float x) { return 1.f / (1.f + __expf(-x)); }
__device__ __forceinline__ float tanhf_(float x) {
    float t = __expf(-2.f * x);
    return (1.f - t) * (1.f / (1.f + t));
}

// ---------------- pack kernels ---------------------------------------------
__global__ void __launch_bounds__(256) pack_A(const float* __restrict__ x,
                                              const float* __restrict__ h) {
    int i = blockIdx.x * 256 + threadIdx.x;
    int b = i >> 8;
    int k = (i & 255) << 2;
    float4 vx = *reinterpret_cast<const float4*>(x + (size_t)b * IN_DIM + k);
    float4 vh = *reinterpret_cast<const float4*>(h + (size_t)b * H_DIM + k);
    __half2* dx = reinterpret_cast<__half2*>(g_A + (size_t)b * KTOT + k);
    dx[0] = __floats2half2_rn(vx.x, vx.y);
    dx[1] = __floats2half2_rn(vx.z, vx.w);
    __half2* dh = reinterpret_cast<__half2*>(g_A + (size_t)b * KTOT + IN_DIM + k);
    dh[0] = __floats2half2_rn(vh.x, vh.y);
    dh[1] = __floats2half2_rn(vh.z, vh.w);
}

__global__ void __launch_bounds__(256) pack_W(
    const float* __restrict__ Wix, const float* __restrict__ Wfx,
    const float* __restrict__ Wgx, const float* __restrict__ Wox,
    const float* __restrict__ Wih, const float* __restrict__ Wfh,
    const float* __restrict__ Wgh, const float* __restrict__ Woh) {
    int i = blockIdx.x * 256 + threadIdx.x;
    int n = i >> 9;
    int k = (i & 511) << 2;
    int r = n >> 2;
    int g = n & 3;
    const float* src;
    if (k < IN_DIM) {
        const float* w = (g == 0) ? Wix : (g == 1) ? Wfx : (g == 2) ? Wgx : Wox;
        src = w + (size_t)r * IN_DIM + k;
    } else {
        const float* w = (g == 0) ? Wih : (g == 1) ? Wfh : (g == 2) ? Wgh : Woh;
        src = w + (size_t)r * H_DIM + (k - IN_DIM);
    }
    float4 v = *reinterpret_cast<const float4*>(src);
    __half2* d = reinterpret_cast<__half2*>(g_W + (size_t)n * KTOT + k);
    d[0] = __floats2half2_rn(v.x, v.y);
    d[1] = __floats2half2_rn(v.z, v.w);
}

__global__ void __launch_bounds__(256) pack_bias(
    const float* __restrict__ bi, const float* __restrict__ bf,
    const float* __restrict__ bg, const float* __restrict__ bo) {
    int i = blockIdx.x * 256 + threadIdx.x;
    int r = i >> 2;
    int g = i & 3;
    const float* b = (g == 0) ? bi : (g == 1) ? bf : (g == 2) ? bg : bo;
    g_bias[i] = b[r];
}

// ---------------- GEMM + fused LSTM epilogue --------------------------------
// CTA tile M=128 x N=128(packed) x K=32, 4-stage cp.async pipeline.
// smem stage: A 128 rows x 40 halves (pad) = 10240B, B same. 20480B/stage.
static constexpr int STAGES   = 4;
static constexpr int ROW_B    = 80;       // bytes per padded smem row (40 halves)
static constexpr int A_BYTES  = 128 * ROW_B;
static constexpr int STAGE_B  = 2 * A_BYTES;
static constexpr int SMEM_DYN = STAGES * STAGE_B;   // 81920
static constexpr int KITERS   = KTOT / 32;          // 64

__global__ void __launch_bounds__(256, 2) lstm_gemm(
    const float* __restrict__ c_prev, float* __restrict__ out) {
    extern __shared__ __align__(128) char smem[];
    const uint32_t sbase = smem_u32(smem);

    const int tid = threadIdx.x;
    const int l   = tid & 31;
    const int wid = tid >> 5;
    const int wm  = wid >> 1;          // 0..3 : 32-row slice
    const int wn  = wid & 1;           // 0..1 : 64-packed-col slice
    const int bn  = blockIdx.x;        // 0..31
    const int bm  = blockIdx.y;        // 0..63

    // ---- global load pattern: thread -> (row, 16B chunk), rows r and r+64
    const int grow = tid >> 2;
    const int gch  = tid & 3;
    const __half* gA = g_A + (size_t)(bm * 128 + grow) * KTOT + gch * 8;
    const __half* gB = g_W + (size_t)(bn * 128 + grow) * KTOT + gch * 8;
    const uint32_t smA = sbase + grow * ROW_B + gch * 16;
    const uint32_t smB = smA + A_BYTES;

    // ---- ldmatrix lane address patterns
    const uint32_t laA = sbase + (uint32_t)(wm * 32 + (l & 7) + 8 * ((l >> 3) & 1)) * ROW_B
                       + (uint32_t)(l >> 4) * 16;
    const uint32_t laB = sbase + A_BYTES
                       + (uint32_t)(wn * 64 + (l & 7) + 8 * (l >> 4)) * ROW_B
                       + (uint32_t)((l >> 3) & 1) * 16;

    float acc[2][8][4];
#pragma unroll
    for (int mb = 0; mb < 2; mb++)
#pragma unroll
        for (int nb = 0; nb < 8; nb++)
#pragma unroll
            for (int q = 0; q < 4; q++) acc[mb][nb][q] = 0.f;

    // ---- prologue: fill 3 stages
#pragma unroll
    for (int s = 0; s < STAGES - 1; s++) {
        const __half* ga = gA + s * 32;
        const __half* gb = gB + s * 32;
        uint32_t so = (uint32_t)s * STAGE_B;
        CP16(smA + so, ga);
        CP16(smA + so + 64 * ROW_B, ga + (size_t)64 * KTOT);
        CP16(smB + so, gb);
        CP16(smB + so + 64 * ROW_B, gb + (size_t)64 * KTOT);
        CP_COMMIT();
    }

    // ---- main loop
    for (int i = 0; i < KITERS; i++) {
        CP_WAIT(2);
        __syncthreads();

        int kt = i + STAGES - 1;
        if (kt < KITERS) {
            const __half* ga = gA + kt * 32;
            const __half* gb = gB + kt * 32;
            uint32_t so = (uint32_t)(kt & (STAGES - 1)) * STAGE_B;
            CP16(smA + so, ga);
            CP16(smA + so + 64 * ROW_B, ga + (size_t)64 * KTOT);
            CP16(smB + so, gb);
            CP16(smB + so + 64 * ROW_B, gb + (size_t)64 * KTOT);
        }
        CP_COMMIT();

        uint32_t so = (uint32_t)(i & (STAGES - 1)) * STAGE_B;
#pragma unroll
        for (int ks = 0; ks < 2; ks++) {
            uint32_t ao = laA + so + ks * 32;
            uint32_t bo = laB + so + ks * 32;
            uint32_t af[2][4], bf[4][4];
#pragma unroll
            for (int mb = 0; mb < 2; mb++) LDSM_X4(af[mb], ao + mb * 16 * ROW_B);
#pragma unroll
            for (int p = 0; p < 4; p++) LDSM_X4(bf[p], bo + p * 16 * ROW_B);
#pragma unroll
            for (int mb = 0; mb < 2; mb++)
#pragma unroll
                for (int p = 0; p < 4; p++) {
                    MMA16816(acc[mb][2 * p],     af[mb], bf[p][0], bf[p][1]);
                    MMA16816(acc[mb][2 * p + 1], af[mb], bf[p][2], bf[p][3]);
                }
        }
    }
    __syncthreads();   // smem stages now free for epilogue staging

    // ---- stage c_prev tile [128 x 32] into smem (coalesced), stride 34
    float* sh_c = reinterpret_cast<float*>(smem);
    float* sh_h = sh_c + 128 * 34;
    float* sh_n = sh_h + 128 * 34;
#pragma unroll
    for (int it = 0; it < 8; it++) {
        int idx = it * 256 + tid;            // 0..2047 float2 slots
        int row = idx >> 4, seg = idx & 15;
        float2 v = *reinterpret_cast<const float2*>(
            c_prev + (size_t)(bm * 128 + row) * H_DIM + bn * 32 + seg * 2);
        *reinterpret_cast<float2*>(sh_c + row * 34 + seg * 2) = v;
    }
    __syncthreads();

    // ---- fused LSTM epilogue in registers
    const int q = l & 3;
#pragma unroll
    for (int mb = 0; mb < 2; mb++) {
#pragma unroll
        for (int nb = 0; nb < 8; nb++) {
            int colbase = bn * 128 + wn * 64 + nb * 8;
            float2 bb = *reinterpret_cast<const float2*>(g_bias + colbase + 2 * q);
            float a0 = acc[mb][nb][0] + bb.x;
            float a1 = acc[mb][nb][1] + bb.y;
            float a2 = acc[mb][nb][2] + bb.x;
            float a3 = acc[mb][nb][3] + bb.y;
            float r0 = __shfl_xor_sync(0xFFFFFFFFu, a0, 1);
            float r1 = __shfl_xor_sync(0xFFFFFFFFu, a1, 1);
            float r2 = __shfl_xor_sync(0xFFFFFFFFu, a2, 1);
            float r3 = __shfl_xor_sync(0xFFFFFFFFu, a3, 1);
            bool ev = (l & 1) == 0;          // even lane: row r0, odd: row r0+8
            float zi = ev ? a0 : r2;
            float zf = ev ? a1 : r3;
            float zg = ev ? r0 : a2;
            float zo = ev ? r1 : a3;
            int rl   = wm * 32 + mb * 16 + ((l >> 2) & 7) + (l & 1) * 8;
            int hcol = wn * 16 + nb * 2 + ((l >> 1) & 1);
            float cp = sh_c[rl * 34 + hcol];
            float gi = sigf(zi), gf = sigf(zf);
            float gg = tanhf_(zg), go = sigf(zo);
            float cn = gf * cp + gi * gg;
            float hn = go * tanhf_(cn);
            sh_h[rl * 34 + hcol] = hn;
            sh_n[rl * 34 + hcol] = cn;
        }
    }
    __syncthreads();

    // ---- coalesced stores
    float* oh = out + (size_t)(bm * 128) * H_DIM + bn * 32;
    float* oc = oh + (size_t)BH;
#pragma unroll
    for (int it = 0; it < 8; it++) {
        int idx = it * 256 + tid;
        int row = idx >> 4, seg = idx & 15;
        float2 vh = *reinterpret_cast<const float2*>(sh_h + row * 34 + seg * 2);
        float2 vc = *reinterpret_cast<const float2*>(sh_n + row * 34 + seg * 2);
        *reinterpret_cast<float2*>(oh + (size_t)row * H_DIM + seg * 2) = vh;
        *reinterpret_cast<float2*>(oc + (size_t)row * H_DIM + seg * 2) = vc;
    }
}

// ---------------- host side -------------------------------------------------
extern "C" void kernel_launch(void* const* d_in, const int* in_sizes, int n_in,
                              void* d_out, int out_size) {
    const float* x   = (const float*)d_in[0];
    const float* h   = (const float*)d_in[1];
    const float* cp  = (const float*)d_in[2];
    const float* Wfx = (const float*)d_in[3];
    const float* bf  = (const float*)d_in[4];
    const float* Wfh = (const float*)d_in[5];
    const float* Wix = (const float*)d_in[6];
    const float* bi  = (const float*)d_in[7];
    const float* Wih = (const float*)d_in[8];
    const float* Wgx = (const float*)d_in[9];
    const float* bg  = (const float*)d_in[10];
    const float* Wgh = (const float*)d_in[11];
    const float* Wox = (const float*)d_in[12];
    const float* bo  = (const float*)d_in[13];
    const float* Woh = (const float*)d_in[14];

    pack_A<<<8192, 256>>>(x, h);
    pack_W<<<8192, 256>>>(Wix, Wfx, Wgx, Wox, Wih, Wfh, Wgh, Woh);
    pack_bias<<<16, 256>>>(bi, bf, bg, bo);

    static bool attr_set = false;
    if (!attr_set) {
        cudaFuncSetAttribute(lstm_gemm, cudaFuncAttributeMaxDynamicSharedMemorySize, SMEM_DYN);
        attr_set = true;
    }
    lstm_gemm<<<dim3(N4H / 128, B_DIM / 128), 256, SMEM_DYN>>>(cp, (float*)d_out);
}